// round 3
// baseline (speedup 1.0000x reference)
#include <cuda_runtime.h>

// out[bh][q*96+v] = K[bh,3,q] * u[bh][v]
//   u[v] = scale * sum_i t[i] * W3[i,v],  t[i] = sum_k Q[bh,3,k] * V[bh][k,i]
//
// Kernel A: 192 blocks compute u  -> g_u scratch (73 KB)
// Kernel B: 1536 blocks stream the outer-product write (7 MB)

#define SD 96
#define NG 8
#define SPAN 12   // 96 / 8
#define NBH 192

__device__ float g_u[NBH * SD];   // scratch: u per (b,h), scale folded in
__device__ float g_k[NBH * SD];   // scratch: K[bh,3,:] rows staged for kernel B

__global__ __launch_bounds__(SD * NG) void compute_u_kernel(
    const float* __restrict__ Q,
    const float* __restrict__ K,
    const float* __restrict__ V,
    const float* __restrict__ DW,
    const int*   __restrict__ uidx_p)
{
    const int bh  = blockIdx.x;       // 0..191
    const int col = threadIdx.x;      // 0..95
    const int grp = threadIdx.y;      // 0..7

    __shared__ float q_s[SD];
    __shared__ float t_s[SD];
    __shared__ float part[NG][SD];

    const float* __restrict__ Vb = V + (size_t)bh * SD * SD;
    const float* __restrict__ W  = DW + (size_t)(*uidx_p) * SD * SD;

    // prefetch V and W slices (independent of q/t)
    float v_r[SPAN], w_r[SPAN];
    #pragma unroll
    for (int j = 0; j < SPAN; ++j) {
        const int k = grp * SPAN + j;
        v_r[j] = Vb[k * SD + col];
        w_r[j] = W [k * SD + col];
    }

    if (grp == 0) {
        const size_t qk_base = ((size_t)bh * SD + 3) * SD;
        q_s[col] = Q[qk_base + col];
        g_k[bh * SD + col] = K[qk_base + col];   // stage K row for kernel B
    }
    __syncthreads();

    // phase 1: t[col] = sum_k q[k] * V[k,col]
    {
        float a = 0.0f;
        #pragma unroll
        for (int j = 0; j < SPAN; ++j)
            a += q_s[grp * SPAN + j] * v_r[j];
        part[grp][col] = a;
    }
    __syncthreads();
    if (grp == 0) {
        float s = 0.0f;
        #pragma unroll
        for (int g = 0; g < NG; ++g) s += part[g][col];
        t_s[col] = s;
    }
    __syncthreads();

    // phase 2: u[col] = scale * sum_i t[i] * W[i,col]
    {
        float a = 0.0f;
        #pragma unroll
        for (int j = 0; j < SPAN; ++j)
            a += t_s[grp * SPAN + j] * w_r[j];
        part[grp][col] = a;
    }
    __syncthreads();
    if (grp == 0) {
        float s = 0.0f;
        #pragma unroll
        for (int g = 0; g < NG; ++g) s += part[g][col];
        g_u[bh * SD + col] = s * rsqrtf(96.0f);
    }
}

// 2304 float4 per bh, split into 8 chunks of 288; one float4 store per thread.
#define CHUNKS 8
#define BTH 288

__global__ __launch_bounds__(BTH) void outer_kernel(float* __restrict__ out)
{
    const int bh    = blockIdx.x / CHUNKS;
    const int chunk = blockIdx.x % CHUNKS;
    const int tid   = threadIdx.x;            // 0..287

    const int p  = chunk * BTH + tid;         // 0..2303 (float4 index in bh tile)
    const int q  = p / 24;                    // row 0..95
    const int v4 = p % 24;                    // float4 col 0..23

    const float  kq = __ldg(&g_k[bh * SD + q]);
    const float4 u4 = __ldg(((const float4*)&g_u[bh * SD]) + v4);

    float4 r;
    r.x = kq * u4.x;  r.y = kq * u4.y;
    r.z = kq * u4.z;  r.w = kq * u4.w;

    ((float4*)(out + (size_t)bh * SD * SD))[p] = r;
}

extern "C" void kernel_launch(void* const* d_in, const int* in_sizes, int n_in,
                              void* d_out, int out_size)
{
    const float* Q  = (const float*)d_in[0];
    const float* K  = (const float*)d_in[1];
    const float* V  = (const float*)d_in[2];
    const float* DW = (const float*)d_in[3];
    const int* uidx = (const int*)d_in[4];
    float* out      = (float*)d_out;

    dim3 blkA(SD, NG);
    compute_u_kernel<<<NBH, blkA>>>(Q, K, V, DW, uidx);
    outer_kernel<<<NBH * CHUNKS, BTH>>>(out);
}

// round 4
// speedup vs baseline: 1.2294x; 1.2294x over previous
#include <cuda_runtime.h>

// out[bh][q*96+v] = K[bh,3,q] * u[bh][v]
//   u[v] = scale * sum_i t[i] * W3[i,v],  t[i] = sum_k Q[bh,3,k] * V[bh][k,i]
//
// 384 blocks (2 per bh), 384 threads (96 cols x 4 groups).
// Both blocks of a bh compute u redundantly (2nd gets L2 hits on V/W);
// each stores its 48-row half of the 96x96 output tile.

#define SD   96
#define NG   4
#define SPAN 24      // 96 / NG
#define NBH  192

__global__ __launch_bounds__(SD * NG, 3) void mma73_kernel(
    const float* __restrict__ Q,
    const float* __restrict__ K,
    const float* __restrict__ V,
    const float* __restrict__ DW,
    const int*   __restrict__ uidx_p,
    float* __restrict__ out)
{
    const int bh  = blockIdx.x >> 1;      // 0..191
    const int sub = blockIdx.x & 1;       // output half
    const int col = threadIdx.x;          // 0..95
    const int grp = threadIdx.y;          // 0..3
    const int lin = grp * SD + col;       // 0..383

    __shared__ float q_s[SD];
    __shared__ float k_s[SD];
    __shared__ float t_s[SD];
    __shared__ __align__(16) float u_s[SD];
    __shared__ float part[NG][SD];

    const float* __restrict__ Vb = V + (size_t)bh * SD * SD;

    // ---- prefetch all 24 V values for this thread (independent of anything) ----
    float v_r[SPAN];
    #pragma unroll
    for (int j = 0; j < SPAN; ++j)
        v_r[j] = Vb[(grp * SPAN + j) * SD + col];

    // uidx load overlaps V latency
    const int uidx = *uidx_p;
    const float* __restrict__ W = DW + (size_t)uidx * SD * SD;

    if (grp == 0) {
        const size_t qk_base = ((size_t)bh * SD + 3) * SD;
        q_s[col] = Q[qk_base + col];
        k_s[col] = K[qk_base + col];
    }
    __syncthreads();

    // ---- phase 1: t[col] = sum_k q[k] * V[k,col] ----
    {
        float a = 0.0f;
        #pragma unroll
        for (int j = 0; j < SPAN; ++j)
            a += q_s[grp * SPAN + j] * v_r[j];
        part[grp][col] = a;
    }

    // start W loads now (overlap the reduce barrier)
    float w_r[SPAN];
    #pragma unroll
    for (int j = 0; j < SPAN; ++j)
        w_r[j] = W[(grp * SPAN + j) * SD + col];

    __syncthreads();
    if (grp == 0) {
        t_s[col] = part[0][col] + part[1][col] + part[2][col] + part[3][col];
    }
    __syncthreads();

    // ---- phase 2: u[col] = scale * sum_i t[i] * W[i,col] ----
    {
        float a = 0.0f;
        #pragma unroll
        for (int j = 0; j < SPAN; ++j)
            a += t_s[grp * SPAN + j] * w_r[j];
        part[grp][col] = a;
    }
    __syncthreads();
    if (grp == 0) {
        u_s[col] = (part[0][col] + part[1][col] + part[2][col] + part[3][col])
                   * rsqrtf(96.0f);
    }
    __syncthreads();

    // ---- phase 3: store this block's 48 rows, float4 ----
    // 48 rows x 24 float4 = 1152 float4 over 384 threads = 3 each.
    float4* __restrict__ O4 = (float4*)(out + (size_t)bh * SD * SD);
    const float4* __restrict__ U4 = (const float4*)u_s;
    const int q0 = sub * 48;
    #pragma unroll
    for (int r = 0; r < 3; ++r) {
        const int p  = lin + r * (SD * NG);   // 0..1151
        const int q  = p / 24;                // 0..47
        const int c4 = p % 24;
        const float  kq = k_s[q0 + q];
        const float4 u4 = U4[c4];
        float4 o;
        o.x = kq * u4.x;  o.y = kq * u4.y;
        o.z = kq * u4.z;  o.w = kq * u4.w;
        O4[(q0 + q) * 24 + c4] = o;
    }
}

extern "C" void kernel_launch(void* const* d_in, const int* in_sizes, int n_in,
                              void* d_out, int out_size)
{
    const float* Q  = (const float*)d_in[0];
    const float* K  = (const float*)d_in[1];
    const float* V  = (const float*)d_in[2];
    const float* DW = (const float*)d_in[3];
    const int* uidx = (const int*)d_in[4];
    float* out      = (float*)d_out;

    dim3 blk(SD, NG);
    mma73_kernel<<<NBH * 2, blk>>>(Q, K, V, DW, uidx, out);
}

// round 5
// speedup vs baseline: 1.2657x; 1.0295x over previous
#include <cuda_runtime.h>

// out[bh][q*96+v] = K[bh,3,q] * u[v];  u = scale * (q3 @ V) @ W3
// 192 blocks (one per bh), 384 threads = 24 float4-cols x 16 k-groups.
// All global traffic as float4.

#define SD    96
#define C4    24     // float4 columns per row
#define KG    16     // k groups
#define KSPAN 6      // 96 / KG
#define NT    (C4 * KG)  // 384

__global__ __launch_bounds__(NT, 2) void mma73_kernel(
    const float* __restrict__ Q,
    const float* __restrict__ K,
    const float* __restrict__ V,
    const float* __restrict__ DW,
    const int*   __restrict__ uidx_p,
    float* __restrict__ out)
{
    const int tid = threadIdx.x;
    const int c4  = tid % C4;      // float4 column group 0..23
    const int grp = tid / C4;      // k group 0..15
    const int bh  = blockIdx.x;    // 0..191

    __shared__ float q_s[SD];
    __shared__ float k_s[SD];
    __shared__ float t_s[SD];
    __shared__ __align__(16) float u_s[SD];
    __shared__ __align__(16) float part[KG][SD];

    // uidx first: its latency overlaps the V load issue below
    const int uidx = *uidx_p;

    const float4* __restrict__ Vb4 = (const float4*)(V + (size_t)bh * SD * SD);
    const float4* __restrict__ W4  = (const float4*)(DW + (size_t)uidx * SD * SD);

    // prefetch: 6 float4 of V and 6 float4 of W per thread (independent loads)
    float4 v_r[KSPAN], w_r[KSPAN];
    #pragma unroll
    for (int j = 0; j < KSPAN; ++j)
        v_r[j] = Vb4[(grp * KSPAN + j) * C4 + c4];
    #pragma unroll
    for (int j = 0; j < KSPAN; ++j)
        w_r[j] = W4[(grp * KSPAN + j) * C4 + c4];

    if (tid < SD) {
        const size_t qk = ((size_t)bh * SD + 3) * SD;
        q_s[tid] = Q[qk + tid];
        k_s[tid] = K[qk + tid];
    }
    __syncthreads();

    // ---- phase 1: t = q3 @ V ----
    {
        float4 a = make_float4(0.f, 0.f, 0.f, 0.f);
        #pragma unroll
        for (int j = 0; j < KSPAN; ++j) {
            const float qk = q_s[grp * KSPAN + j];
            a.x += qk * v_r[j].x;  a.y += qk * v_r[j].y;
            a.z += qk * v_r[j].z;  a.w += qk * v_r[j].w;
        }
        ((float4*)part[grp])[c4] = a;
    }
    __syncthreads();
    if (tid < SD) {
        float s = 0.f;
        #pragma unroll
        for (int g = 0; g < KG; ++g) s += part[g][tid];
        t_s[tid] = s;
    }
    __syncthreads();

    // ---- phase 2: u = scale * (t @ W3) ----
    {
        float4 a = make_float4(0.f, 0.f, 0.f, 0.f);
        #pragma unroll
        for (int j = 0; j < KSPAN; ++j) {
            const float ti = t_s[grp * KSPAN + j];
            a.x += ti * w_r[j].x;  a.y += ti * w_r[j].y;
            a.z += ti * w_r[j].z;  a.w += ti * w_r[j].w;
        }
        ((float4*)part[grp])[c4] = a;
    }
    __syncthreads();
    if (tid < SD) {
        float s = 0.f;
        #pragma unroll
        for (int g = 0; g < KG; ++g) s += part[g][tid];
        u_s[tid] = s * 0.10206207261596575f;   // 1/sqrt(96)
    }
    __syncthreads();

    // ---- phase 3: outer product, 6 float4 stores per thread ----
    // row q = r*16 + grp, col group c4; each warp writes a contiguous 512B span
    float4* __restrict__ O4 = (float4*)(out + (size_t)bh * SD * SD);
    const float4 u4 = ((const float4*)u_s)[c4];
    #pragma unroll
    for (int r = 0; r < KSPAN; ++r) {
        const int q = r * KG + grp;
        const float kq = k_s[q];
        float4 o;
        o.x = kq * u4.x;  o.y = kq * u4.y;
        o.z = kq * u4.z;  o.w = kq * u4.w;
        O4[q * C4 + c4] = o;
    }
}

extern "C" void kernel_launch(void* const* d_in, const int* in_sizes, int n_in,
                              void* d_out, int out_size)
{
    const float* Q  = (const float*)d_in[0];
    const float* K  = (const float*)d_in[1];
    const float* V  = (const float*)d_in[2];
    const float* DW = (const float*)d_in[3];
    const int* uidx = (const int*)d_in[4];
    float* out      = (float*)d_out;

    mma73_kernel<<<192, NT>>>(Q, K, V, DW, uidx, out);
}